// round 13
// baseline (speedup 1.0000x reference)
#include <cuda_runtime.h>
#include <math.h>

#define BQ   4
#define SQ   1024
#define NH   32
#define NKV  8
#define HD   128
#define DIMM 4096
#define NTOK (BQ*SQ)   // 4096 tokens

// Scratch (static device globals: allocation-free at kernel_launch time)
__device__ float g_q[(size_t)NTOK*NH*HD];     // [b,s,h,d]  64 MB
__device__ float g_k[(size_t)NTOK*NKV*HD];    // [b,s,kv,d] 16 MB
__device__ float g_v[(size_t)NTOK*NKV*HD];    // 16 MB
__device__ float g_attn[(size_t)NTOK*NH*HD];  // 64 MB

// ---------------------------------------------------------------------------
// Classic fp32 SGEMM: C[M,N] = A[M,K] @ B[K,N], row-major.
// 128x128 block tile, BK=8, 256 threads, 8x8 per-thread micro-tile.
// Requires M%128==0, N%128==0, K%8==0 (true for all our shapes).
// ---------------------------------------------------------------------------
__global__ __launch_bounds__(256) void sgemm128(
    const float* __restrict__ A, const float* __restrict__ B,
    float* __restrict__ C, int M, int N, int K)
{
    __shared__ float As[8][128];   // transposed A tile
    __shared__ float Bs[8][128];

    const int tid  = threadIdx.x;
    const int arow = tid >> 1;            // 0..127
    const int acol = (tid & 1) << 2;      // 0 or 4
    const int brl  = tid >> 5;            // 0..7
    const int bcl  = (tid & 31) << 2;     // 0..124
    const int ty   = tid >> 4;            // 0..15
    const int tx   = tid & 15;            // 0..15

    const float* Ap = A + (size_t)(blockIdx.y * 128 + arow) * K + acol;
    const float* Bp = B + (size_t)brl * N + blockIdx.x * 128 + bcl;

    float acc[8][8];
#pragma unroll
    for (int i = 0; i < 8; i++)
#pragma unroll
        for (int j = 0; j < 8; j++) acc[i][j] = 0.f;

    for (int k0 = 0; k0 < K; k0 += 8) {
        float4 a = *(const float4*)Ap;  Ap += 8;
        float4 b = *(const float4*)Bp;  Bp += (size_t)8 * N;
        As[acol + 0][arow] = a.x;
        As[acol + 1][arow] = a.y;
        As[acol + 2][arow] = a.z;
        As[acol + 3][arow] = a.w;
        *(float4*)&Bs[brl][bcl] = b;
        __syncthreads();

#pragma unroll
        for (int k = 0; k < 8; k++) {
            float ra[8], rb[8];
            *(float4*)&ra[0] = *(const float4*)&As[k][ty * 8];
            *(float4*)&ra[4] = *(const float4*)&As[k][ty * 8 + 4];
            *(float4*)&rb[0] = *(const float4*)&Bs[k][tx * 8];
            *(float4*)&rb[4] = *(const float4*)&Bs[k][tx * 8 + 4];
#pragma unroll
            for (int i = 0; i < 8; i++)
#pragma unroll
                for (int j = 0; j < 8; j++)
                    acc[i][j] = fmaf(ra[i], rb[j], acc[i][j]);
        }
        __syncthreads();
    }

    float* Cp = C + (size_t)(blockIdx.y * 128 + ty * 8) * N + blockIdx.x * 128 + tx * 8;
#pragma unroll
    for (int i = 0; i < 8; i++) {
        *(float4*)(Cp)     = make_float4(acc[i][0], acc[i][1], acc[i][2], acc[i][3]);
        *(float4*)(Cp + 4) = make_float4(acc[i][4], acc[i][5], acc[i][6], acc[i][7]);
        Cp += N;
    }
}

// ---------------------------------------------------------------------------
// RoPE (interleaved-pair convention, matching the reference _rope):
//   out[2i]   = t[2i]*cos - t[2i+1]*sin
//   out[2i+1] = t[2i]*sin + t[2i+1]*cos
// t layout: [b, s, nheads, 128]; cos/sin: [S, 64]
// ---------------------------------------------------------------------------
__global__ __launch_bounds__(256) void rope_kernel(
    float* __restrict__ t, const float* __restrict__ cosd,
    const float* __restrict__ sind, int nheads)
{
    long idx = (long)blockIdx.x * blockDim.x + threadIdx.x;
    long total = (long)NTOK * nheads * 64;
    if (idx >= total) return;
    int  d2  = (int)(idx & 63);
    long rest = idx >> 6;
    int  h   = (int)(rest % nheads);
    long bs  = rest / nheads;             // b*S + s
    int  s   = (int)(bs & (SQ - 1));
    float c  = cosd[s * 64 + d2];
    float sn = sind[s * 64 + d2];
    size_t base = ((size_t)bs * nheads + h) * HD + (size_t)d2 * 2;
    float te = t[base], to = t[base + 1];
    t[base]     = te * c - to * sn;
    t[base + 1] = te * sn + to * c;
}

// ---------------------------------------------------------------------------
// Causal GQA attention (flash style), fp32.
// Grid: (S/64, NH, B). Block: 256 threads (16x16, 4x4 score tile, 4x8 O tile).
// smem: Qs[128][64] d-major, Ks[128][64] d-major, Vs[64][128], Ps[64][64].
// ---------------------------------------------------------------------------
__global__ __launch_bounds__(256) void attn_kernel()
{
    extern __shared__ float sm[];
    float* Qs = sm;            // 8192 floats
    float* Ks = sm + 8192;     // 8192
    float* Vs = sm + 16384;    // 8192
    float* Ps = sm + 24576;    // 4096   -> total 28672 floats = 112 KB

    const int tid = threadIdx.x;
    const int qb  = blockIdx.x;
    const int h   = blockIdx.y;
    const int b   = blockIdx.z;
    const int kvh = h >> 2;                 // n_rep = 4
    const int q0  = qb * 64;
    const int ty  = tid >> 4;               // 0..15 -> rows ty*4..ty*4+3
    const int tx  = tid & 15;               // 0..15 -> score cols tx*4.., O cols tx*8..

    // Load Q tile, store d-major (transposed)
    for (int t = tid; t < 2048; t += 256) {
        int r  = t >> 5;
        int d4 = (t & 31) << 2;
        float4 v = *(const float4*)&g_q[(((size_t)(b * SQ + q0 + r)) * NH + h) * HD + d4];
        Qs[(d4 + 0) * 64 + r] = v.x;
        Qs[(d4 + 1) * 64 + r] = v.y;
        Qs[(d4 + 2) * 64 + r] = v.z;
        Qs[(d4 + 3) * 64 + r] = v.w;
    }

    float acc[4][8];
#pragma unroll
    for (int i = 0; i < 4; i++)
#pragma unroll
        for (int j = 0; j < 8; j++) acc[i][j] = 0.f;
    float m[4] = {-INFINITY, -INFINITY, -INFINITY, -INFINITY};
    float l[4] = {0.f, 0.f, 0.f, 0.f};
    const float sc = 0.08838834764831845f;   // 1/sqrt(128)

    for (int kb = 0; kb <= qb; kb++) {
        __syncthreads();   // previous iter's PV reads done (also covers Qs stores)
        // Load K (d-major) and V (row-major) tiles
        for (int t = tid; t < 2048; t += 256) {
            int r  = t >> 5;
            int d4 = (t & 31) << 2;
            size_t gi = (((size_t)(b * SQ + kb * 64 + r)) * NKV + kvh) * HD + d4;
            float4 kv = *(const float4*)&g_k[gi];
            Ks[(d4 + 0) * 64 + r] = kv.x;
            Ks[(d4 + 1) * 64 + r] = kv.y;
            Ks[(d4 + 2) * 64 + r] = kv.z;
            Ks[(d4 + 3) * 64 + r] = kv.w;
            *(float4*)&Vs[r * HD + d4] = *(const float4*)&g_v[gi];
        }
        __syncthreads();

        // Scores: S[i][j] = sum_d Q[d][ty*4+i] * K[d][tx*4+j]
        float s_acc[4][4];
#pragma unroll
        for (int i = 0; i < 4; i++)
#pragma unroll
            for (int j = 0; j < 4; j++) s_acc[i][j] = 0.f;
#pragma unroll 4
        for (int d = 0; d < 128; d++) {
            float4 qa = *(const float4*)&Qs[d * 64 + ty * 4];
            float4 ka = *(const float4*)&Ks[d * 64 + tx * 4];
            float qv[4] = {qa.x, qa.y, qa.z, qa.w};
            float kv[4] = {ka.x, ka.y, ka.z, ka.w};
#pragma unroll
            for (int i = 0; i < 4; i++)
#pragma unroll
                for (int j = 0; j < 4; j++)
                    s_acc[i][j] = fmaf(qv[i], kv[j], s_acc[i][j]);
        }

        // Scale + causal mask (diagonal block only)
        if (kb == qb) {
#pragma unroll
            for (int i = 0; i < 4; i++)
#pragma unroll
                for (int j = 0; j < 4; j++)
                    s_acc[i][j] = (tx * 4 + j > ty * 4 + i) ? -INFINITY : s_acc[i][j] * sc;
        } else {
#pragma unroll
            for (int i = 0; i < 4; i++)
#pragma unroll
                for (int j = 0; j < 4; j++) s_acc[i][j] *= sc;
        }

        // Online softmax update (row reductions across the 16 tx lanes)
#pragma unroll
        for (int i = 0; i < 4; i++) {
            float mx = fmaxf(fmaxf(s_acc[i][0], s_acc[i][1]),
                             fmaxf(s_acc[i][2], s_acc[i][3]));
            mx = fmaxf(mx, __shfl_xor_sync(0xffffffffu, mx, 8));
            mx = fmaxf(mx, __shfl_xor_sync(0xffffffffu, mx, 4));
            mx = fmaxf(mx, __shfl_xor_sync(0xffffffffu, mx, 2));
            mx = fmaxf(mx, __shfl_xor_sync(0xffffffffu, mx, 1));
            float mn = fmaxf(m[i], mx);
            float p0 = __expf(s_acc[i][0] - mn);
            float p1 = __expf(s_acc[i][1] - mn);
            float p2 = __expf(s_acc[i][2] - mn);
            float p3 = __expf(s_acc[i][3] - mn);
            float rs = (p0 + p1) + (p2 + p3);
            rs += __shfl_xor_sync(0xffffffffu, rs, 8);
            rs += __shfl_xor_sync(0xffffffffu, rs, 4);
            rs += __shfl_xor_sync(0xffffffffu, rs, 2);
            rs += __shfl_xor_sync(0xffffffffu, rs, 1);
            float scale = __expf(m[i] - mn);   // exp(-inf - finite) = 0 on first block
            m[i] = mn;
            l[i] = l[i] * scale + rs;
#pragma unroll
            for (int j = 0; j < 8; j++) acc[i][j] *= scale;
            *(float4*)&Ps[(ty * 4 + i) * 64 + tx * 4] = make_float4(p0, p1, p2, p3);
        }
        __syncthreads();

        // O += P @ V
#pragma unroll 2
        for (int k = 0; k < 64; k++) {
            float p[4];
#pragma unroll
            for (int i = 0; i < 4; i++) p[i] = Ps[(ty * 4 + i) * 64 + k];
            float4 v0 = *(const float4*)&Vs[k * HD + tx * 8];
            float4 v1 = *(const float4*)&Vs[k * HD + tx * 8 + 4];
            float vv[8] = {v0.x, v0.y, v0.z, v0.w, v1.x, v1.y, v1.z, v1.w};
#pragma unroll
            for (int i = 0; i < 4; i++)
#pragma unroll
                for (int j = 0; j < 8; j++)
                    acc[i][j] = fmaf(p[i], vv[j], acc[i][j]);
        }
    }

    // Epilogue: normalize and store to g_attn [b, s, h, d]
#pragma unroll
    for (int i = 0; i < 4; i++) {
        float inv = 1.f / l[i];
        size_t base = (((size_t)(b * SQ + q0 + ty * 4 + i)) * NH + h) * HD + tx * 8;
        *(float4*)&g_attn[base] =
            make_float4(acc[i][0] * inv, acc[i][1] * inv, acc[i][2] * inv, acc[i][3] * inv);
        *(float4*)&g_attn[base + 4] =
            make_float4(acc[i][4] * inv, acc[i][5] * inv, acc[i][6] * inv, acc[i][7] * inv);
    }
}

// ---------------------------------------------------------------------------
// Launcher
// ---------------------------------------------------------------------------
extern "C" void kernel_launch(void* const* d_in, const int* in_sizes, int n_in,
                              void* d_out, int out_size)
{
    const float* x  = (const float*)d_in[0];
    const float* wq = (const float*)d_in[1];
    const float* wk = (const float*)d_in[2];
    const float* wv = (const float*)d_in[3];
    const float* wo = (const float*)d_in[4];
    const float* fc = (const float*)d_in[5];
    const float* fs = (const float*)d_in[6];
    // d_in[7] = causal_mask (standard triu -inf; causality implemented directly)
    // d_in[8] = fixed_point_iter (0), d_in[9] = start_pos (0)
    float* out = (float*)d_out;

    float *q, *k, *v, *attn;
    cudaGetSymbolAddress((void**)&q,    g_q);
    cudaGetSymbolAddress((void**)&k,    g_k);
    cudaGetSymbolAddress((void**)&v,    g_v);
    cudaGetSymbolAddress((void**)&attn, g_attn);

    dim3 blk(256);

    // QKV projections
    sgemm128<<<dim3(DIMM / 128, NTOK / 128), blk>>>(x, wq, q, NTOK, DIMM, DIMM);
    sgemm128<<<dim3((NKV * HD) / 128, NTOK / 128), blk>>>(x, wk, k, NTOK, NKV * HD, DIMM);
    sgemm128<<<dim3((NKV * HD) / 128, NTOK / 128), blk>>>(x, wv, v, NTOK, NKV * HD, DIMM);

    // RoPE on Q and K
    rope_kernel<<<(NTOK * NH * 64) / 256, blk>>>(q, fc, fs, NH);
    rope_kernel<<<(NTOK * NKV * 64) / 256, blk>>>(k, fc, fs, NKV);

    // Attention
    cudaFuncSetAttribute(attn_kernel, cudaFuncAttributeMaxDynamicSharedMemorySize, 114688);
    attn_kernel<<<dim3(SQ / 64, NH, BQ), blk, 114688>>>();

    // Output projection
    sgemm128<<<dim3(DIMM / 128, NTOK / 128), blk>>>(attn, wo, out, NTOK, DIMM, DIMM);
}

// round 14
// speedup vs baseline: 2.6424x; 2.6424x over previous
#include <cuda_runtime.h>
#include <math.h>
#include <stdint.h>

#define BQ   4
#define SQ   1024
#define NH   32
#define NKV  8
#define HD   128
#define DIMM 4096
#define NTOK (BQ*SQ)   // 4096 tokens

// Scratch (static device globals: allocation-free at kernel_launch time)
__device__ float g_q[(size_t)NTOK*NH*HD];     // [b,s,h,d]  64 MB
__device__ float g_k[(size_t)NTOK*NKV*HD];    // [b,s,kv,d] 16 MB
__device__ float g_v[(size_t)NTOK*NKV*HD];    // 16 MB
__device__ float g_attn[(size_t)NTOK*NH*HD];  // 64 MB

// ---------------------------------------------------------------------------
// TF32 tensor-core GEMM: C[M,N] = A[M,K] @ B[K,N], row-major fp32 in/out.
// CTA tile 128x128, BK=32, 256 threads (8 warps), warp tile 64x32.
// mma.sync.aligned.m16n8k8.row.col.f32.tf32.tf32.f32
// Requires M%128==0, N%128==0, K%32==0.
// ---------------------------------------------------------------------------
#define ASTR 36    // A smem row stride (== 4 mod 32 -> conflict-free frags)
#define BSTR 136   // B smem row stride (== 8 mod 32 -> conflict-free frags)

__device__ __forceinline__ uint32_t f2tf32(float x) {
    uint32_t r;
    asm("cvt.rna.tf32.f32 %0, %1;" : "=r"(r) : "f"(x));
    return r;
}

__device__ __forceinline__ void mma_tf32(float* c, const uint32_t* a, const uint32_t* b) {
    asm volatile(
        "mma.sync.aligned.m16n8k8.row.col.f32.tf32.tf32.f32 "
        "{%0,%1,%2,%3}, {%4,%5,%6,%7}, {%8,%9}, {%0,%1,%2,%3};\n"
        : "+f"(c[0]), "+f"(c[1]), "+f"(c[2]), "+f"(c[3])
        : "r"(a[0]), "r"(a[1]), "r"(a[2]), "r"(a[3]), "r"(b[0]), "r"(b[1]));
}

__global__ __launch_bounds__(256) void gemm_tf32(
    const float* __restrict__ A, const float* __restrict__ B,
    float* __restrict__ C, int M, int N, int K)
{
    __shared__ uint32_t As[128 * ASTR];   // [m][k] tf32
    __shared__ uint32_t Bs[32 * BSTR];    // [k][n] tf32

    const int tid  = threadIdx.x;
    const int warp = tid >> 5;
    const int lane = tid & 31;
    const int wm   = (warp & 1) * 64;     // warp M offset
    const int wn   = (warp >> 1) * 32;    // warp N offset
    const int g    = lane >> 2;           // 0..7
    const int t4   = lane & 3;            // 0..3

    const int m0 = blockIdx.y * 128;
    const int n0 = blockIdx.x * 128;

    // A loader: thread handles rows am + 32*i, float4 col ac
    const int am = tid >> 3;              // 0..31
    const int ac = tid & 7;               // 0..7

    float acc[4][4][4];
#pragma unroll
    for (int i = 0; i < 4; i++)
#pragma unroll
        for (int j = 0; j < 4; j++)
#pragma unroll
            for (int r = 0; r < 4; r++) acc[i][j][r] = 0.f;

    const float* Ag = A + (size_t)(m0 + am) * K + ac * 4;
    const float* Bg = B + (size_t)warp * N + n0 + lane * 4;   // row=warp(+8i), col=lane*4

    for (int k0 = 0; k0 < K; k0 += 32) {
        // Load A tile 128x32 (float4, coalesced), convert to tf32
#pragma unroll
        for (int i = 0; i < 4; i++) {
            float4 v = *(const float4*)(Ag + (size_t)(i * 32) * K + k0);
            uint32_t* p = &As[(am + i * 32) * ASTR + ac * 4];
            p[0] = f2tf32(v.x); p[1] = f2tf32(v.y);
            p[2] = f2tf32(v.z); p[3] = f2tf32(v.w);
        }
        // Load B tile 32x128 (float4, coalesced)
#pragma unroll
        for (int i = 0; i < 4; i++) {
            float4 v = *(const float4*)(Bg + (size_t)(k0 + i * 8) * N);
            uint32_t* p = &Bs[(warp + i * 8) * BSTR + lane * 4];
            p[0] = f2tf32(v.x); p[1] = f2tf32(v.y);
            p[2] = f2tf32(v.z); p[3] = f2tf32(v.w);
        }
        __syncthreads();

#pragma unroll
        for (int kk = 0; kk < 32; kk += 8) {
            uint32_t af[4][4], bf[4][2];
#pragma unroll
            for (int im = 0; im < 4; im++) {
                const uint32_t* base = &As[(wm + im * 16 + g) * ASTR + kk + t4];
                af[im][0] = base[0];
                af[im][1] = base[8 * ASTR];
                af[im][2] = base[4];
                af[im][3] = base[8 * ASTR + 4];
            }
#pragma unroll
            for (int jn = 0; jn < 4; jn++) {
                const uint32_t* base = &Bs[(kk + t4) * BSTR + wn + jn * 8 + g];
                bf[jn][0] = base[0];
                bf[jn][1] = base[4 * BSTR];
            }
#pragma unroll
            for (int im = 0; im < 4; im++)
#pragma unroll
                for (int jn = 0; jn < 4; jn++)
                    mma_tf32(acc[im][jn], af[im], bf[jn]);
        }
        __syncthreads();
    }

    // Epilogue
#pragma unroll
    for (int im = 0; im < 4; im++) {
        int r0 = m0 + wm + im * 16 + g;
#pragma unroll
        for (int jn = 0; jn < 4; jn++) {
            int c0 = n0 + wn + jn * 8 + 2 * t4;
            *(float2*)&C[(size_t)r0 * N + c0] =
                make_float2(acc[im][jn][0], acc[im][jn][1]);
            *(float2*)&C[(size_t)(r0 + 8) * N + c0] =
                make_float2(acc[im][jn][2], acc[im][jn][3]);
        }
    }
}

// ---------------------------------------------------------------------------
// RoPE (interleaved-pair convention, matching the reference _rope)
// ---------------------------------------------------------------------------
__global__ __launch_bounds__(256) void rope_kernel(
    float* __restrict__ t, const float* __restrict__ cosd,
    const float* __restrict__ sind, int nheads)
{
    long idx = (long)blockIdx.x * blockDim.x + threadIdx.x;
    long total = (long)NTOK * nheads * 64;
    if (idx >= total) return;
    int  d2  = (int)(idx & 63);
    long rest = idx >> 6;
    int  h   = (int)(rest % nheads);
    long bs  = rest / nheads;             // b*S + s
    int  s   = (int)(bs & (SQ - 1));
    float c  = cosd[s * 64 + d2];
    float sn = sind[s * 64 + d2];
    size_t base = ((size_t)bs * nheads + h) * HD + (size_t)d2 * 2;
    float te = t[base], to = t[base + 1];
    t[base]     = te * c - to * sn;
    t[base + 1] = te * sn + to * c;
}

// ---------------------------------------------------------------------------
// Causal GQA attention (flash style), fp32. Unchanged from R13 (passing).
// ---------------------------------------------------------------------------
__global__ __launch_bounds__(256) void attn_kernel()
{
    extern __shared__ float sm[];
    float* Qs = sm;            // 8192 floats
    float* Ks = sm + 8192;     // 8192
    float* Vs = sm + 16384;    // 8192
    float* Ps = sm + 24576;    // 4096   -> total 28672 floats = 112 KB

    const int tid = threadIdx.x;
    const int qb  = blockIdx.x;
    const int h   = blockIdx.y;
    const int b   = blockIdx.z;
    const int kvh = h >> 2;                 // n_rep = 4
    const int q0  = qb * 64;
    const int ty  = tid >> 4;
    const int tx  = tid & 15;

    for (int t = tid; t < 2048; t += 256) {
        int r  = t >> 5;
        int d4 = (t & 31) << 2;
        float4 v = *(const float4*)&g_q[(((size_t)(b * SQ + q0 + r)) * NH + h) * HD + d4];
        Qs[(d4 + 0) * 64 + r] = v.x;
        Qs[(d4 + 1) * 64 + r] = v.y;
        Qs[(d4 + 2) * 64 + r] = v.z;
        Qs[(d4 + 3) * 64 + r] = v.w;
    }

    float acc[4][8];
#pragma unroll
    for (int i = 0; i < 4; i++)
#pragma unroll
        for (int j = 0; j < 8; j++) acc[i][j] = 0.f;
    float m[4] = {-INFINITY, -INFINITY, -INFINITY, -INFINITY};
    float l[4] = {0.f, 0.f, 0.f, 0.f};
    const float sc = 0.08838834764831845f;

    for (int kb = 0; kb <= qb; kb++) {
        __syncthreads();
        for (int t = tid; t < 2048; t += 256) {
            int r  = t >> 5;
            int d4 = (t & 31) << 2;
            size_t gi = (((size_t)(b * SQ + kb * 64 + r)) * NKV + kvh) * HD + d4;
            float4 kv = *(const float4*)&g_k[gi];
            Ks[(d4 + 0) * 64 + r] = kv.x;
            Ks[(d4 + 1) * 64 + r] = kv.y;
            Ks[(d4 + 2) * 64 + r] = kv.z;
            Ks[(d4 + 3) * 64 + r] = kv.w;
            *(float4*)&Vs[r * HD + d4] = *(const float4*)&g_v[gi];
        }
        __syncthreads();

        float s_acc[4][4];
#pragma unroll
        for (int i = 0; i < 4; i++)
#pragma unroll
            for (int j = 0; j < 4; j++) s_acc[i][j] = 0.f;
#pragma unroll 4
        for (int d = 0; d < 128; d++) {
            float4 qa = *(const float4*)&Qs[d * 64 + ty * 4];
            float4 ka = *(const float4*)&Ks[d * 64 + tx * 4];
            float qv[4] = {qa.x, qa.y, qa.z, qa.w};
            float kv[4] = {ka.x, ka.y, ka.z, ka.w};
#pragma unroll
            for (int i = 0; i < 4; i++)
#pragma unroll
                for (int j = 0; j < 4; j++)
                    s_acc[i][j] = fmaf(qv[i], kv[j], s_acc[i][j]);
        }

        if (kb == qb) {
#pragma unroll
            for (int i = 0; i < 4; i++)
#pragma unroll
                for (int j = 0; j < 4; j++)
                    s_acc[i][j] = (tx * 4 + j > ty * 4 + i) ? -INFINITY : s_acc[i][j] * sc;
        } else {
#pragma unroll
            for (int i = 0; i < 4; i++)
#pragma unroll
                for (int j = 0; j < 4; j++) s_acc[i][j] *= sc;
        }

#pragma unroll
        for (int i = 0; i < 4; i++) {
            float mx = fmaxf(fmaxf(s_acc[i][0], s_acc[i][1]),
                             fmaxf(s_acc[i][2], s_acc[i][3]));
            mx = fmaxf(mx, __shfl_xor_sync(0xffffffffu, mx, 8));
            mx = fmaxf(mx, __shfl_xor_sync(0xffffffffu, mx, 4));
            mx = fmaxf(mx, __shfl_xor_sync(0xffffffffu, mx, 2));
            mx = fmaxf(mx, __shfl_xor_sync(0xffffffffu, mx, 1));
            float mn = fmaxf(m[i], mx);
            float p0 = __expf(s_acc[i][0] - mn);
            float p1 = __expf(s_acc[i][1] - mn);
            float p2 = __expf(s_acc[i][2] - mn);
            float p3 = __expf(s_acc[i][3] - mn);
            float rs = (p0 + p1) + (p2 + p3);
            rs += __shfl_xor_sync(0xffffffffu, rs, 8);
            rs += __shfl_xor_sync(0xffffffffu, rs, 4);
            rs += __shfl_xor_sync(0xffffffffu, rs, 2);
            rs += __shfl_xor_sync(0xffffffffu, rs, 1);
            float scale = __expf(m[i] - mn);
            m[i] = mn;
            l[i] = l[i] * scale + rs;
#pragma unroll
            for (int j = 0; j < 8; j++) acc[i][j] *= scale;
            *(float4*)&Ps[(ty * 4 + i) * 64 + tx * 4] = make_float4(p0, p1, p2, p3);
        }
        __syncthreads();

#pragma unroll 2
        for (int k = 0; k < 64; k++) {
            float p[4];
#pragma unroll
            for (int i = 0; i < 4; i++) p[i] = Ps[(ty * 4 + i) * 64 + k];
            float4 v0 = *(const float4*)&Vs[k * HD + tx * 8];
            float4 v1 = *(const float4*)&Vs[k * HD + tx * 8 + 4];
            float vv[8] = {v0.x, v0.y, v0.z, v0.w, v1.x, v1.y, v1.z, v1.w};
#pragma unroll
            for (int i = 0; i < 4; i++)
#pragma unroll
                for (int j = 0; j < 8; j++)
                    acc[i][j] = fmaf(p[i], vv[j], acc[i][j]);
        }
    }

#pragma unroll
    for (int i = 0; i < 4; i++) {
        float inv = 1.f / l[i];
        size_t base = (((size_t)(b * SQ + q0 + ty * 4 + i)) * NH + h) * HD + tx * 8;
        *(float4*)&g_attn[base] =
            make_float4(acc[i][0] * inv, acc[i][1] * inv, acc[i][2] * inv, acc[i][3] * inv);
        *(float4*)&g_attn[base + 4] =
            make_float4(acc[i][4] * inv, acc[i][5] * inv, acc[i][6] * inv, acc[i][7] * inv);
    }
}

// ---------------------------------------------------------------------------
// Launcher
// ---------------------------------------------------------------------------
extern "C" void kernel_launch(void* const* d_in, const int* in_sizes, int n_in,
                              void* d_out, int out_size)
{
    const float* x  = (const float*)d_in[0];
    const float* wq = (const float*)d_in[1];
    const float* wk = (const float*)d_in[2];
    const float* wv = (const float*)d_in[3];
    const float* wo = (const float*)d_in[4];
    const float* fc = (const float*)d_in[5];
    const float* fs = (const float*)d_in[6];
    float* out = (float*)d_out;

    float *q, *k, *v, *attn;
    cudaGetSymbolAddress((void**)&q,    g_q);
    cudaGetSymbolAddress((void**)&k,    g_k);
    cudaGetSymbolAddress((void**)&v,    g_v);
    cudaGetSymbolAddress((void**)&attn, g_attn);

    dim3 blk(256);

    // QKV projections (tf32 tensor cores)
    gemm_tf32<<<dim3(DIMM / 128, NTOK / 128), blk>>>(x, wq, q, NTOK, DIMM, DIMM);
    gemm_tf32<<<dim3((NKV * HD) / 128, NTOK / 128), blk>>>(x, wk, k, NTOK, NKV * HD, DIMM);
    gemm_tf32<<<dim3((NKV * HD) / 128, NTOK / 128), blk>>>(x, wv, v, NTOK, NKV * HD, DIMM);

    // RoPE on Q and K
    rope_kernel<<<(NTOK * NH * 64) / 256, blk>>>(q, fc, fs, NH);
    rope_kernel<<<(NTOK * NKV * 64) / 256, blk>>>(k, fc, fs, NKV);

    // Attention
    cudaFuncSetAttribute(attn_kernel, cudaFuncAttributeMaxDynamicSharedMemorySize, 114688);
    attn_kernel<<<dim3(SQ / 64, NH, BQ), blk, 114688>>>();

    // Output projection (tf32 tensor cores)
    gemm_tf32<<<dim3(DIMM / 128, NTOK / 128), blk>>>(attn, wo, out, NTOK, DIMM, DIMM);
}

// round 15
// speedup vs baseline: 4.0605x; 1.5367x over previous
#include <cuda_runtime.h>
#include <math.h>
#include <stdint.h>

#define BQ   4
#define SQ   1024
#define NH   32
#define NKV  8
#define HD   128
#define DIMM 4096
#define NTOK (BQ*SQ)   // 4096 tokens

// Scratch (static device globals: allocation-free at kernel_launch time)
__device__ float g_q[(size_t)NTOK*NH*HD];     // [b,s,h,d]  64 MB
__device__ float g_k[(size_t)NTOK*NKV*HD];    // 16 MB
__device__ float g_v[(size_t)NTOK*NKV*HD];    // 16 MB
__device__ float g_attn[(size_t)NTOK*NH*HD];  // 64 MB

__device__ __forceinline__ uint32_t f2tf32(float x) {
    uint32_t r;
    asm("cvt.rna.tf32.f32 %0, %1;" : "=r"(r) : "f"(x));
    return r;
}

__device__ __forceinline__ void mma_tf32(float* c, const uint32_t* a, const uint32_t* b) {
    asm volatile(
        "mma.sync.aligned.m16n8k8.row.col.f32.tf32.tf32.f32 "
        "{%0,%1,%2,%3}, {%4,%5,%6,%7}, {%8,%9}, {%0,%1,%2,%3};\n"
        : "+f"(c[0]), "+f"(c[1]), "+f"(c[2]), "+f"(c[3])
        : "r"(a[0]), "r"(a[1]), "r"(a[2]), "r"(a[3]), "r"(b[0]), "r"(b[1]));
}

// ---------------------------------------------------------------------------
// TF32 tensor-core GEMM, software-pipelined (reg double-buffer + 2 smem bufs).
// C[M,N] = A[M,K] @ B[K,N], row-major fp32. CTA 128x128, BK=32, 256 threads.
// ---------------------------------------------------------------------------
#define ASTR 36
#define BSTR 136
#define ABUF (128*ASTR)
#define BBUF (32*BSTR)
#define GEMM_SMEM ((2*ABUF + 2*BBUF)*4)

__global__ __launch_bounds__(256) void gemm_tf32(
    const float* __restrict__ A, const float* __restrict__ B,
    float* __restrict__ C, int M, int N, int K)
{
    extern __shared__ uint32_t smu[];
    uint32_t* As = smu;              // [2][128][ASTR]
    uint32_t* Bs = smu + 2*ABUF;     // [2][32][BSTR]

    const int tid  = threadIdx.x;
    const int warp = tid >> 5;
    const int lane = tid & 31;
    const int wm   = (warp & 1) * 64;
    const int wn   = (warp >> 1) * 32;
    const int g    = lane >> 2;
    const int t4   = lane & 3;

    const int m0 = blockIdx.y * 128;
    const int n0 = blockIdx.x * 128;

    const int am = tid >> 3;              // 0..31
    const int ac = tid & 7;               // 0..7

    float acc[4][4][4];
#pragma unroll
    for (int i = 0; i < 4; i++)
#pragma unroll
        for (int j = 0; j < 4; j++)
#pragma unroll
            for (int r = 0; r < 4; r++) acc[i][j][r] = 0.f;

    const float* Ag = A + (size_t)(m0 + am) * K + ac * 4;
    const float* Bg = B + (size_t)warp * N + n0 + lane * 4;

    float4 ra[4], rb[4];
    // Preload k0 = 0
#pragma unroll
    for (int i = 0; i < 4; i++) ra[i] = *(const float4*)(Ag + (size_t)(i * 32) * K);
#pragma unroll
    for (int i = 0; i < 4; i++) rb[i] = *(const float4*)(Bg + (size_t)(i * 8) * N);
    {
        uint32_t* Aw = As;  uint32_t* Bw = Bs;
#pragma unroll
        for (int i = 0; i < 4; i++) {
            uint32_t* p = &Aw[(am + i * 32) * ASTR + ac * 4];
            p[0] = f2tf32(ra[i].x); p[1] = f2tf32(ra[i].y);
            p[2] = f2tf32(ra[i].z); p[3] = f2tf32(ra[i].w);
        }
#pragma unroll
        for (int i = 0; i < 4; i++) {
            uint32_t* p = &Bw[(warp + i * 8) * BSTR + lane * 4];
            p[0] = f2tf32(rb[i].x); p[1] = f2tf32(rb[i].y);
            p[2] = f2tf32(rb[i].z); p[3] = f2tf32(rb[i].w);
        }
    }
    __syncthreads();

    int buf = 0;
    for (int k0 = 0; k0 < K; k0 += 32) {
        const bool more = (k0 + 32) < K;
        if (more) {
#pragma unroll
            for (int i = 0; i < 4; i++)
                ra[i] = *(const float4*)(Ag + (size_t)(i * 32) * K + (k0 + 32));
#pragma unroll
            for (int i = 0; i < 4; i++)
                rb[i] = *(const float4*)(Bg + (size_t)(k0 + 32 + i * 8) * N);
        }

        const uint32_t* Ab = As + buf * ABUF;
        const uint32_t* Bb = Bs + buf * BBUF;
#pragma unroll
        for (int kk = 0; kk < 32; kk += 8) {
            uint32_t af[4][4], bf[4][2];
#pragma unroll
            for (int im = 0; im < 4; im++) {
                const uint32_t* base = &Ab[(wm + im * 16 + g) * ASTR + kk + t4];
                af[im][0] = base[0];
                af[im][1] = base[8 * ASTR];
                af[im][2] = base[4];
                af[im][3] = base[8 * ASTR + 4];
            }
#pragma unroll
            for (int jn = 0; jn < 4; jn++) {
                const uint32_t* base = &Bb[(kk + t4) * BSTR + wn + jn * 8 + g];
                bf[jn][0] = base[0];
                bf[jn][1] = base[4 * BSTR];
            }
#pragma unroll
            for (int im = 0; im < 4; im++)
#pragma unroll
                for (int jn = 0; jn < 4; jn++)
                    mma_tf32(acc[im][jn], af[im], bf[jn]);
        }

        if (more) {
            uint32_t* Aw = As + (buf ^ 1) * ABUF;
            uint32_t* Bw = Bs + (buf ^ 1) * BBUF;
#pragma unroll
            for (int i = 0; i < 4; i++) {
                uint32_t* p = &Aw[(am + i * 32) * ASTR + ac * 4];
                p[0] = f2tf32(ra[i].x); p[1] = f2tf32(ra[i].y);
                p[2] = f2tf32(ra[i].z); p[3] = f2tf32(ra[i].w);
            }
#pragma unroll
            for (int i = 0; i < 4; i++) {
                uint32_t* p = &Bw[(warp + i * 8) * BSTR + lane * 4];
                p[0] = f2tf32(rb[i].x); p[1] = f2tf32(rb[i].y);
                p[2] = f2tf32(rb[i].z); p[3] = f2tf32(rb[i].w);
            }
            __syncthreads();
            buf ^= 1;
        }
    }

#pragma unroll
    for (int im = 0; im < 4; im++) {
        int r0 = m0 + wm + im * 16 + g;
#pragma unroll
        for (int jn = 0; jn < 4; jn++) {
            int c0 = n0 + wn + jn * 8 + 2 * t4;
            *(float2*)&C[(size_t)r0 * N + c0] =
                make_float2(acc[im][jn][0], acc[im][jn][1]);
            *(float2*)&C[(size_t)(r0 + 8) * N + c0] =
                make_float2(acc[im][jn][2], acc[im][jn][3]);
        }
    }
}

// ---------------------------------------------------------------------------
// RoPE (interleaved-pair convention)
// ---------------------------------------------------------------------------
__global__ __launch_bounds__(256) void rope_kernel(
    float* __restrict__ t, const float* __restrict__ cosd,
    const float* __restrict__ sind, int nheads)
{
    long idx = (long)blockIdx.x * blockDim.x + threadIdx.x;
    long total = (long)NTOK * nheads * 64;
    if (idx >= total) return;
    int  d2  = (int)(idx & 63);
    long rest = idx >> 6;
    int  h   = (int)(rest % nheads);
    long bs  = rest / nheads;
    int  s   = (int)(bs & (SQ - 1));
    float c  = cosd[s * 64 + d2];
    float sn = sind[s * 64 + d2];
    size_t base = ((size_t)bs * nheads + h) * HD + (size_t)d2 * 2;
    float te = t[base], to = t[base + 1];
    t[base]     = te * c - to * sn;
    t[base + 1] = te * sn + to * c;
}

// ---------------------------------------------------------------------------
// Causal GQA flash attention on tf32 mma.sync.
// Grid (SQ/128, NH, BQ), 256 threads (8 warps, 16 q-rows/warp).
// smem (tf32/uint32): Qs[128][132], Ks[64][132], Vs[64][136], Ps[128][68]
// ---------------------------------------------------------------------------
#define QSTR 132
#define KSTR 132
#define VSTR 136
#define PSTR 68
#define ATTN_SMEM ((128*QSTR + 64*KSTR + 64*VSTR + 128*PSTR)*4)

__global__ __launch_bounds__(256, 1) void attn_mma()
{
    extern __shared__ uint32_t smu[];
    uint32_t* Qs = smu;                       // [128][QSTR]
    uint32_t* Ks = Qs + 128 * QSTR;           // [64][KSTR]
    uint32_t* Vs = Ks + 64 * KSTR;            // [64][VSTR]
    uint32_t* Ps = Vs + 64 * VSTR;            // [128][PSTR]

    const int tid  = threadIdx.x;
    const int warp = tid >> 5;
    const int lane = tid & 31;
    const int g    = lane >> 2;
    const int t4   = lane & 3;
    const int qb   = blockIdx.x;
    const int h    = blockIdx.y;
    const int b    = blockIdx.z;
    const int kvh  = h >> 2;
    const int q0   = qb * 128;
    const int wr   = warp * 16;

    // Load Q tile (128 x 128), convert to tf32
    for (int t = tid; t < 128 * 32; t += 256) {
        int r  = t >> 5;
        int d4 = (t & 31) << 2;
        float4 v = *(const float4*)&g_q[(((size_t)(b * SQ + q0 + r)) * NH + h) * HD + d4];
        uint4 u = make_uint4(f2tf32(v.x), f2tf32(v.y), f2tf32(v.z), f2tf32(v.w));
        *(uint4*)&Qs[r * QSTR + d4] = u;
    }

    float oacc[16][4];
#pragma unroll
    for (int j = 0; j < 16; j++)
#pragma unroll
        for (int r = 0; r < 4; r++) oacc[j][r] = 0.f;
    float mrow0 = -INFINITY, mrow1 = -INFINITY, lrow0 = 0.f, lrow1 = 0.f;

    const float sc = 0.08838834764831845f;    // 1/sqrt(128)
    const int r0a = q0 + wr + g;
    const int r1a = r0a + 8;
    const int nkb = 2 * qb + 2;

    for (int kb = 0; kb < nkb; kb++) {
        __syncthreads();   // prior PV reads of Vs/Ps finished; Qs stores covered on iter 0
        // Load K/V tile (64 x 128 each), convert to tf32
        for (int t = tid; t < 64 * 32; t += 256) {
            int r  = t >> 5;
            int d4 = (t & 31) << 2;
            size_t gi = (((size_t)(b * SQ + kb * 64 + r)) * NKV + kvh) * HD + d4;
            float4 kf = *(const float4*)&g_k[gi];
            float4 vf = *(const float4*)&g_v[gi];
            *(uint4*)&Ks[r * KSTR + d4] =
                make_uint4(f2tf32(kf.x), f2tf32(kf.y), f2tf32(kf.z), f2tf32(kf.w));
            *(uint4*)&Vs[r * VSTR + d4] =
                make_uint4(f2tf32(vf.x), f2tf32(vf.y), f2tf32(vf.z), f2tf32(vf.w));
        }
        __syncthreads();

        // S = Q @ K^T  (8 n-tiles of 8 keys, 16 k-steps over d)
        float sacc[8][4];
#pragma unroll
        for (int j = 0; j < 8; j++)
#pragma unroll
            for (int r = 0; r < 4; r++) sacc[j][r] = 0.f;
#pragma unroll
        for (int kk = 0; kk < 128; kk += 8) {
            uint32_t af[4];
            const uint32_t* qp = &Qs[(wr + g) * QSTR + kk + t4];
            af[0] = qp[0];
            af[1] = qp[8 * QSTR];
            af[2] = qp[4];
            af[3] = qp[8 * QSTR + 4];
#pragma unroll
            for (int j = 0; j < 8; j++) {
                uint32_t bfr[2];
                const uint32_t* kp = &Ks[(j * 8 + g) * KSTR + kk + t4];
                bfr[0] = kp[0];
                bfr[1] = kp[4];
                mma_tf32(sacc[j], af, bfr);
            }
        }

        // Scale + causal mask (only diagonal blocks need masking)
        if (kb >= 2 * qb) {
#pragma unroll
            for (int j = 0; j < 8; j++)
#pragma unroll
                for (int c = 0; c < 2; c++) {
                    int col = kb * 64 + j * 8 + 2 * t4 + c;
                    sacc[j][c]     = (col > r0a) ? -INFINITY : sacc[j][c] * sc;
                    sacc[j][c + 2] = (col > r1a) ? -INFINITY : sacc[j][c + 2] * sc;
                }
        } else {
#pragma unroll
            for (int j = 0; j < 8; j++)
#pragma unroll
                for (int r = 0; r < 4; r++) sacc[j][r] *= sc;
        }

        // Online softmax (rows r0a, r1a; reduce across t4 via intra-quad shfl)
        float mx0 = -INFINITY, mx1 = -INFINITY;
#pragma unroll
        for (int j = 0; j < 8; j++) {
            mx0 = fmaxf(mx0, fmaxf(sacc[j][0], sacc[j][1]));
            mx1 = fmaxf(mx1, fmaxf(sacc[j][2], sacc[j][3]));
        }
        mx0 = fmaxf(mx0, __shfl_xor_sync(0xffffffffu, mx0, 1));
        mx0 = fmaxf(mx0, __shfl_xor_sync(0xffffffffu, mx0, 2));
        mx1 = fmaxf(mx1, __shfl_xor_sync(0xffffffffu, mx1, 1));
        mx1 = fmaxf(mx1, __shfl_xor_sync(0xffffffffu, mx1, 2));
        float mn0 = fmaxf(mrow0, mx0);
        float mn1 = fmaxf(mrow1, mx1);

        float rs0 = 0.f, rs1 = 0.f;
#pragma unroll
        for (int j = 0; j < 8; j++) {
            float p0 = __expf(sacc[j][0] - mn0);
            float p1 = __expf(sacc[j][1] - mn0);
            float p2 = __expf(sacc[j][2] - mn1);
            float p3 = __expf(sacc[j][3] - mn1);
            rs0 += p0 + p1;
            rs1 += p2 + p3;
            *(uint2*)&Ps[(wr + g) * PSTR + j * 8 + 2 * t4] =
                make_uint2(f2tf32(p0), f2tf32(p1));
            *(uint2*)&Ps[(wr + g + 8) * PSTR + j * 8 + 2 * t4] =
                make_uint2(f2tf32(p2), f2tf32(p3));
        }
        rs0 += __shfl_xor_sync(0xffffffffu, rs0, 1);
        rs0 += __shfl_xor_sync(0xffffffffu, rs0, 2);
        rs1 += __shfl_xor_sync(0xffffffffu, rs1, 1);
        rs1 += __shfl_xor_sync(0xffffffffu, rs1, 2);

        float e0 = __expf(mrow0 - mn0);   // 0 on first block
        float e1 = __expf(mrow1 - mn1);
        mrow0 = mn0; mrow1 = mn1;
        lrow0 = lrow0 * e0 + rs0;
        lrow1 = lrow1 * e1 + rs1;
#pragma unroll
        for (int jd = 0; jd < 16; jd++) {
            oacc[jd][0] *= e0; oacc[jd][1] *= e0;
            oacc[jd][2] *= e1; oacc[jd][3] *= e1;
        }
        __syncthreads();   // Ps visible

        // O += P @ V  (16 n-tiles over d, 8 k-steps over keys)
#pragma unroll
        for (int kk2 = 0; kk2 < 64; kk2 += 8) {
            uint32_t af[4];
            const uint32_t* pp = &Ps[(wr + g) * PSTR + kk2 + t4];
            af[0] = pp[0];
            af[1] = pp[8 * PSTR];
            af[2] = pp[4];
            af[3] = pp[8 * PSTR + 4];
#pragma unroll
            for (int jd = 0; jd < 16; jd++) {
                uint32_t bfr[2];
                const uint32_t* vp = &Vs[(kk2 + t4) * VSTR + jd * 8 + g];
                bfr[0] = vp[0];
                bfr[1] = vp[4 * VSTR];
                mma_tf32(oacc[jd], af, bfr);
            }
        }
    }

    // Epilogue: normalize and store to g_attn [b, s, h, d] (fp32)
    float inv0 = 1.f / lrow0;
    float inv1 = 1.f / lrow1;
    size_t base0 = (((size_t)(b * SQ + q0 + wr + g)) * NH + h) * HD;
    size_t base1 = base0 + (size_t)8 * NH * HD;
#pragma unroll
    for (int jd = 0; jd < 16; jd++) {
        int c = jd * 8 + 2 * t4;
        *(float2*)&g_attn[base0 + c] = make_float2(oacc[jd][0] * inv0, oacc[jd][1] * inv0);
        *(float2*)&g_attn[base1 + c] = make_float2(oacc[jd][2] * inv1, oacc[jd][3] * inv1);
    }
}

// ---------------------------------------------------------------------------
// Launcher
// ---------------------------------------------------------------------------
extern "C" void kernel_launch(void* const* d_in, const int* in_sizes, int n_in,
                              void* d_out, int out_size)
{
    const float* x  = (const float*)d_in[0];
    const float* wq = (const float*)d_in[1];
    const float* wk = (const float*)d_in[2];
    const float* wv = (const float*)d_in[3];
    const float* wo = (const float*)d_in[4];
    const float* fc = (const float*)d_in[5];
    const float* fs = (const float*)d_in[6];
    float* out = (float*)d_out;

    float *q, *k, *v, *attn;
    cudaGetSymbolAddress((void**)&q,    g_q);
    cudaGetSymbolAddress((void**)&k,    g_k);
    cudaGetSymbolAddress((void**)&v,    g_v);
    cudaGetSymbolAddress((void**)&attn, g_attn);

    cudaFuncSetAttribute(gemm_tf32, cudaFuncAttributeMaxDynamicSharedMemorySize, GEMM_SMEM);
    cudaFuncSetAttribute(attn_mma,  cudaFuncAttributeMaxDynamicSharedMemorySize, ATTN_SMEM);

    dim3 blk(256);

    // QKV projections (tf32 tensor cores, pipelined)
    gemm_tf32<<<dim3(DIMM / 128, NTOK / 128), blk, GEMM_SMEM>>>(x, wq, q, NTOK, DIMM, DIMM);
    gemm_tf32<<<dim3((NKV * HD) / 128, NTOK / 128), blk, GEMM_SMEM>>>(x, wk, k, NTOK, NKV * HD, DIMM);
    gemm_tf32<<<dim3((NKV * HD) / 128, NTOK / 128), blk, GEMM_SMEM>>>(x, wv, v, NTOK, NKV * HD, DIMM);

    // RoPE on Q and K
    rope_kernel<<<(NTOK * NH * 64) / 256, blk>>>(q, fc, fs, NH);
    rope_kernel<<<(NTOK * NKV * 64) / 256, blk>>>(k, fc, fs, NKV);

    // Attention (tf32 tensor cores)
    attn_mma<<<dim3(SQ / 128, NH, BQ), blk, ATTN_SMEM>>>();

    // Output projection
    gemm_tf32<<<dim3(DIMM / 128, NTOK / 128), blk, GEMM_SMEM>>>(attn, wo, out, NTOK, DIMM, DIMM);
}